// round 1
// baseline (speedup 1.0000x reference)
#include <cuda_runtime.h>

// Upsampling_68882685493276: 2x nearest-neighbor upsample
// in : [16, 64, 256, 256] fp32  (B*C = 1024, H = W = 256)
// out: [16, 64, 512, 512] fp32
//
// out[b,c,H,W] = in[b,c,H/2,W/2]
//
// One thread per input float4 (4 consecutive w). Each thread:
//   - 1x LDG.128 (16 B)
//   - expands (a,b,c,d) -> (a,a,b,b) (c,c,d,d)
//   - 4x STG.128 (two float4 per output row, rows 2h and 2h+1)
// Traffic: 256 MiB read + 1 GiB write, every byte touched exactly once.

#define IN_W4   64      // input float4 per row (256 / 4)
#define IN_H    256
#define OUT_W4  128     // output float4 per row (512 / 4)
#define OUT_BC4 65536   // output float4 per (b,c) image (512*512/4)

__global__ __launch_bounds__(256)
void upsample2x_kernel(const float4* __restrict__ in,
                       float4* __restrict__ out,
                       int n4)
{
    int idx = blockIdx.x * blockDim.x + threadIdx.x;
    if (idx >= n4) return;

    int w4 = idx & (IN_W4 - 1);          // input float4 column
    int h  = (idx >> 6) & (IN_H - 1);    // input row
    int bc = idx >> 14;                  // fused batch*channel

    // Streaming load: input is read exactly once.
    float4 v = __ldcs(in + idx);

    float4 lo = make_float4(v.x, v.x, v.y, v.y);
    float4 hi = make_float4(v.z, v.z, v.w, v.w);

    // Output base: image bc, row 2h, column 2*w4 (in float4 units).
    int o = bc * OUT_BC4 + (h << 1) * OUT_W4 + (w4 << 1);

    __stcs(out + o,              lo);
    __stcs(out + o + 1,          hi);
    __stcs(out + o + OUT_W4,     lo);
    __stcs(out + o + OUT_W4 + 1, hi);
}

extern "C" void kernel_launch(void* const* d_in, const int* in_sizes, int n_in,
                              void* d_out, int out_size)
{
    const float4* in  = (const float4*)d_in[0];
    float4*       out = (float4*)d_out;

    int n4 = in_sizes[0] / 4;            // 16,777,216 input float4s
    int threads = 256;
    int blocks  = (n4 + threads - 1) / threads;   // 65,536

    upsample2x_kernel<<<blocks, threads>>>(in, out, n4);
}